// round 1
// baseline (speedup 1.0000x reference)
#include <cuda_runtime.h>

#define HW    192
#define NPIX  36864      // 192*192
#define CH    64
#define WS    48
#define NTOK  2304       // 48*48
#define NWIN  16
#define TOTTOK 36864

// ---------------- scratch (device globals; no allocations) ----------------
__device__ __align__(16) float g_Qt[NWIN*CH*NTOK];   // [win][d][n]
__device__ __align__(16) float g_Kt[NWIN*CH*NTOK];   // [win][d][n]
__device__ __align__(16) float g_V [NWIN*NTOK*CH];   // [token][d]
__device__ __align__(16) float g_U [TOTTOK];
__device__ __align__(16) float g_O [TOTTOK*CH];      // [token][d]
__device__ __align__(16) float g_ref[CH*NPIX];       // NCHW refined
__device__ __align__(16) float g_M [CH*CH];          // fused W1*Wout
__device__ __align__(16) float g_b2[CH];

// ---------------- kernel 1: QKV projections + binarized uncertainty -------
__global__ void __launch_bounds__(128) qkv_kernel(
    const float* __restrict__ x, const float* __restrict__ rf,
    const float* __restrict__ unc,
    const float* __restrict__ ipw, const float* __restrict__ ipb)
{
    __shared__ float Ws[192*64];                       // 48 KB exactly
    int tid = threadIdx.x;
    for (int i = tid; i < 192*64; i += 128) Ws[i] = ipw[i];
    __syncthreads();

    int t   = blockIdx.x*128 + tid;                    // global token
    int win = t / NTOK, n = t % NTOK;
    int hi  = win >> 2, wi = win & 3;
    int si  = n / WS,  sj = n % WS;
    int pix = (hi*WS + si)*HW + wi*WS + sj;

    float v[64];
#pragma unroll
    for (int c = 0; c < 64; c++) v[c] = x[c*NPIX + pix];

    int dbase = win*CH*NTOK + n;                       // d-major per window
    for (int o = 0; o < 64; o++) {
        float acc = ipb[o];
        const float4* wp = (const float4*)&Ws[o*64];
#pragma unroll
        for (int k = 0; k < 16; k++) {
            float4 w = wp[k];
            acc += v[4*k]*w.x + v[4*k+1]*w.y + v[4*k+2]*w.z + v[4*k+3]*w.w;
        }
        g_Qt[dbase + o*NTOK] = acc;
    }

#pragma unroll
    for (int c = 0; c < 64; c++) v[c] = rf[c*NPIX + pix];

    for (int o = 0; o < 64; o++) {
        float acc = ipb[64+o];
        const float4* wp = (const float4*)&Ws[(64+o)*64];
#pragma unroll
        for (int k = 0; k < 16; k++) {
            float4 w = wp[k];
            acc += v[4*k]*w.x + v[4*k+1]*w.y + v[4*k+2]*w.z + v[4*k+3]*w.w;
        }
        g_Kt[dbase + o*NTOK] = acc;
    }
    for (int o = 0; o < 64; o++) {
        float acc = ipb[128+o];
        const float4* wp = (const float4*)&Ws[(128+o)*64];
#pragma unroll
        for (int k = 0; k < 16; k++) {
            float4 w = wp[k];
            acc += v[4*k]*w.x + v[4*k+1]*w.y + v[4*k+2]*w.z + v[4*k+3]*w.w;
        }
        g_V[t*64 + o] = acc;
    }
    g_U[t] = (unc[pix] > 0.01f) ? 1.f : 0.f;
}

// ---------------- kernel 2: flash-style masked attention ------------------
// grid (36 row-tiles, 16 windows), 256 threads, 4x4 register tiles
#define ATTN_SMEM_FLOATS (4096*4 + 128)
__global__ void __launch_bounds__(256) attn_kernel()
{
    extern __shared__ float sm[];
    float* Qs = sm;            // [d][64 rows]
    float* Ks = sm + 4096;     // [d][64 cols]
    float* Vs = sm + 8192;     // [col][d]
    float* Ps = sm + 12288;    // [row][col]
    float* ur = sm + 16384;    // row mask (64)
    float* uc = sm + 16448;    // col mask (64)

    int win = blockIdx.y;
    int r0  = blockIdx.x * 64;
    int tid = threadIdx.x;
    int ty  = tid >> 4, tx = tid & 15;

    const float* Qg = g_Qt + win*CH*NTOK;
    const float* Kg = g_Kt + win*CH*NTOK;
    const float* Vg = g_V  + (size_t)win*NTOK*CH;
    const float* Ug = g_U  + win*NTOK;

#pragma unroll
    for (int it = 0; it < 4; it++) {
        int li = it*256 + tid;
        int d = li >> 4, c4 = li & 15;
        *(float4*)&Qs[d*64 + c4*4] = *(const float4*)&Qg[d*NTOK + r0 + c4*4];
    }
    if (tid < 64) ur[tid] = Ug[r0 + tid];

    float m[4], l[4], o[16];
#pragma unroll
    for (int i = 0; i < 4; i++) { m[i] = -1e30f; l[i] = 0.f; }
#pragma unroll
    for (int i = 0; i < 16; i++) o[i] = 0.f;

    for (int ct = 0; ct < 36; ct++) {
        int c0 = ct * 64;
        __syncthreads();                               // prev iter done with Ks/Vs/Ps
#pragma unroll
        for (int it = 0; it < 4; it++) {
            int li = it*256 + tid;
            int a = li >> 4, c4 = li & 15;
            *(float4*)&Ks[a*64 + c4*4] = *(const float4*)&Kg[a*NTOK + c0 + c4*4];
            *(float4*)&Vs[a*64 + c4*4] = *(const float4*)&Vg[(c0 + a)*64 + c4*4];
        }
        if (tid < 64) uc[tid] = Ug[c0 + tid];
        __syncthreads();

        float s[16];
#pragma unroll
        for (int i = 0; i < 16; i++) s[i] = 0.f;
#pragma unroll 8
        for (int d = 0; d < 64; d++) {
            float4 q4 = *(const float4*)&Qs[d*64 + ty*4];
            float4 k4 = *(const float4*)&Ks[d*64 + tx*4];
            s[0]  += q4.x*k4.x; s[1]  += q4.x*k4.y; s[2]  += q4.x*k4.z; s[3]  += q4.x*k4.w;
            s[4]  += q4.y*k4.x; s[5]  += q4.y*k4.y; s[6]  += q4.y*k4.z; s[7]  += q4.y*k4.w;
            s[8]  += q4.z*k4.x; s[9]  += q4.z*k4.y; s[10] += q4.z*k4.z; s[11] += q4.z*k4.w;
            s[12] += q4.w*k4.x; s[13] += q4.w*k4.y; s[14] += q4.w*k4.z; s[15] += q4.w*k4.w;
        }

        float ucv[4];
#pragma unroll
        for (int j = 0; j < 4; j++) ucv[j] = uc[tx*4 + j];

#pragma unroll
        for (int i = 0; i < 4; i++) {
            float urv = ur[ty*4 + i];
            float p[4];
#pragma unroll
            for (int j = 0; j < 4; j++) {
                float sv = s[i*4+j];
                sv = (urv > 0.5f) ? ((ucv[j] > 0.5f) ? sv*0.125f : -1e30f) : 0.f;
                s[i*4+j] = sv;
            }
            float tm = fmaxf(fmaxf(s[i*4], s[i*4+1]), fmaxf(s[i*4+2], s[i*4+3]));
            tm = fmaxf(tm, __shfl_xor_sync(0xffffffffu, tm, 1));
            tm = fmaxf(tm, __shfl_xor_sync(0xffffffffu, tm, 2));
            tm = fmaxf(tm, __shfl_xor_sync(0xffffffffu, tm, 4));
            tm = fmaxf(tm, __shfl_xor_sync(0xffffffffu, tm, 8));
            float nm  = fmaxf(m[i], tm);
            float fac = __expf(m[i] - nm);
            float rs  = 0.f;
#pragma unroll
            for (int j = 0; j < 4; j++) {
                float sv = s[i*4+j];
                p[j] = (sv < -1e29f) ? 0.f : __expf(sv - nm);
                rs  += p[j];
            }
            rs += __shfl_xor_sync(0xffffffffu, rs, 1);
            rs += __shfl_xor_sync(0xffffffffu, rs, 2);
            rs += __shfl_xor_sync(0xffffffffu, rs, 4);
            rs += __shfl_xor_sync(0xffffffffu, rs, 8);
            l[i] = l[i]*fac + rs;
            m[i] = nm;
#pragma unroll
            for (int j = 0; j < 4; j++) o[i*4+j] *= fac;
            *(float4*)&Ps[(ty*4+i)*64 + tx*4] = make_float4(p[0], p[1], p[2], p[3]);
        }
        __syncwarp();
#pragma unroll 8
        for (int c = 0; c < 64; c++) {
            float4 v4 = *(const float4*)&Vs[c*64 + tx*4];
#pragma unroll
            for (int i = 0; i < 4; i++) {
                float pr = Ps[(ty*4+i)*64 + c];
                o[i*4+0] += pr*v4.x; o[i*4+1] += pr*v4.y;
                o[i*4+2] += pr*v4.z; o[i*4+3] += pr*v4.w;
            }
        }
    }

    int tb = win*NTOK + r0 + ty*4;
#pragma unroll
    for (int i = 0; i < 4; i++) {
        float inv = 1.f / l[i];
        *(float4*)&g_O[(size_t)(tb+i)*64 + tx*4] =
            make_float4(o[i*4]*inv, o[i*4+1]*inv, o[i*4+2]*inv, o[i*4+3]*inv);
    }
}

// ---------------- prep: M = W1*Wout, b2 = W1*bout + b1 --------------------
__global__ void prep_kernel(const float* __restrict__ w1, const float* __restrict__ b1,
                            const float* __restrict__ wo, const float* __restrict__ bo)
{
    int i = blockIdx.x, j = threadIdx.x;
    float acc = 0.f;
    for (int k = 0; k < 64; k++) acc += w1[i*64+k] * wo[k*64+j];
    g_M[i*64+j] = acc;
    if (j == 0) {
        float a = b1[i];
        for (int k = 0; k < 64; k++) a += w1[i*64+k] * bo[k];
        g_b2[i] = a;
    }
}

// ---------------- kernel 3: refined = x + O*M^T + b2 (NCHW) ---------------
__global__ void __launch_bounds__(128) refine_kernel(const float* __restrict__ x)
{
    __shared__ float Ms[4096];
    __shared__ float bs[64];
    int tid = threadIdx.x;
    for (int i = tid; i < 4096; i += 128) Ms[i] = g_M[i];
    if (tid < 64) bs[tid] = g_b2[tid];
    __syncthreads();

    int t   = blockIdx.x*128 + tid;
    int win = t / NTOK, n = t % NTOK;
    int hi  = win >> 2, wi = win & 3;
    int pix = (hi*WS + n/WS)*HW + wi*WS + n%WS;

    float ov[64];
    const float4* op = (const float4*)&g_O[(size_t)t*64];
#pragma unroll
    for (int k = 0; k < 16; k++) {
        float4 q = op[k];
        ov[4*k] = q.x; ov[4*k+1] = q.y; ov[4*k+2] = q.z; ov[4*k+3] = q.w;
    }
    for (int c = 0; c < 64; c++) {
        float acc = bs[c];
        const float4* mp = (const float4*)&Ms[c*64];
#pragma unroll
        for (int k = 0; k < 16; k++) {
            float4 w = mp[k];
            acc += ov[4*k]*w.x + ov[4*k+1]*w.y + ov[4*k+2]*w.z + ov[4*k+3]*w.w;
        }
        g_ref[c*NPIX + pix] = x[c*NPIX + pix] + acc;
    }
}

// ---------------- kernel 4: conv3x3+ReLU, 1x1 head, partition map ---------
#define CONV_SMEM_BYTES ((36864 + 64 + 64) * 4)
__global__ void __launch_bounds__(128) conv_kernel(
    const float* __restrict__ w3, const float* __restrict__ b3,
    const float* __restrict__ w4, const float* __restrict__ b4v,
    float* __restrict__ out)
{
    extern __shared__ float cs[];
    float* Wsm = cs;              // [c][k][o]
    float* b3s = cs + 36864;
    float* w4s = b3s + 64;
    int tid = threadIdx.x;
    for (int i = tid; i < 36864; i += 128) {
        int c = i / 576, r = i % 576, k = r >> 6, o = r & 63;
        Wsm[i] = w3[(o*64 + c)*9 + k];
    }
    if (tid < 64) { b3s[tid] = b3[tid]; w4s[tid] = w4[tid]; }
    __syncthreads();
    float b4 = b4v[0];

    int p0 = blockIdx.x*256 + tid*2;          // two consecutive pixels, same row
    int y  = p0 / HW, x0 = p0 % HW;

    float acc0[64], acc1[64];
#pragma unroll
    for (int o = 0; o < 64; o++) { acc0[o] = 0.f; acc1[o] = 0.f; }

    for (int c = 0; c < 64; c++) {
        const float* rp = g_ref + c*NPIX;
        float in[12];
#pragma unroll
        for (int dy = 0; dy < 3; dy++) {
            int yy = y + dy - 1;
            bool yok = (yy >= 0) && (yy < HW);
#pragma unroll
            for (int dx = 0; dx < 4; dx++) {
                int xx = x0 + dx - 1;
                in[dy*4+dx] = (yok && xx >= 0 && xx < HW) ? __ldg(&rp[yy*HW + xx]) : 0.f;
            }
        }
        const float4* wp = (const float4*)&Wsm[c*576];
#pragma unroll
        for (int k = 0; k < 9; k++) {
            int ky = k/3, kx = k%3;
            float i0 = in[ky*4+kx], i1 = in[ky*4+kx+1];
#pragma unroll
            for (int o4 = 0; o4 < 16; o4++) {
                float4 w = wp[k*16 + o4];
                acc0[o4*4+0] += i0*w.x; acc0[o4*4+1] += i0*w.y;
                acc0[o4*4+2] += i0*w.z; acc0[o4*4+3] += i0*w.w;
                acc1[o4*4+0] += i1*w.x; acc1[o4*4+1] += i1*w.y;
                acc1[o4*4+2] += i1*w.z; acc1[o4*4+3] += i1*w.w;
            }
        }
    }

    float s0 = 0.f, s1 = 0.f;
#pragma unroll
    for (int o = 0; o < 64; o++) {
        float r0v = fmaxf(acc0[o] + b3s[o], 0.f);
        float r1v = fmaxf(acc1[o] + b3s[o], 0.f);
        *(float2*)&out[(size_t)o*NPIX + p0] = make_float2(r0v, r1v);
        s0 += r0v * w4s[o]; s1 += r1v * w4s[o];
    }
    *(float2*)&out[(size_t)64*NPIX + p0] = make_float2(s0 + b4, s1 + b4);

    int ry = y % WS;
    bool by = (ry == 0) || (ry == WS-1);
    int rx0 = x0 % WS, rx1 = (x0+1) % WS;
    float pm0 = (by || rx0 == 0 || rx0 == WS-1) ? 0.6f : 1.0f;
    float pm1 = (by || rx1 == 0 || rx1 == WS-1) ? 0.6f : 1.0f;
    *(float2*)&out[(size_t)65*NPIX + p0] = make_float2(pm0, pm1);
}

// ---------------- launch ---------------------------------------------------
extern "C" void kernel_launch(void* const* d_in, const int* in_sizes, int n_in,
                              void* d_out, int out_size)
{
    const float* x    = (const float*)d_in[0];
    const float* rf   = (const float*)d_in[1];
    const float* unc  = (const float*)d_in[2];
    const float* ipw  = (const float*)d_in[3];
    const float* ipb  = (const float*)d_in[4];
    const float* wout = (const float*)d_in[5];
    const float* bout = (const float*)d_in[6];
    const float* w1   = (const float*)d_in[7];
    const float* b1   = (const float*)d_in[8];
    const float* w3   = (const float*)d_in[9];
    const float* b3   = (const float*)d_in[10];
    const float* w4   = (const float*)d_in[11];
    const float* b4   = (const float*)d_in[12];
    float* out = (float*)d_out;

    static bool attr_set = false;
    if (!attr_set) {
        cudaFuncSetAttribute(attn_kernel, cudaFuncAttributeMaxDynamicSharedMemorySize,
                             ATTN_SMEM_FLOATS * 4);
        cudaFuncSetAttribute(conv_kernel, cudaFuncAttributeMaxDynamicSharedMemorySize,
                             CONV_SMEM_BYTES);
        attr_set = true;
    }

    qkv_kernel<<<288, 128>>>(x, rf, unc, ipw, ipb);
    prep_kernel<<<64, 64>>>(w1, b1, wout, bout);
    dim3 ag(36, 16);
    attn_kernel<<<ag, 256, ATTN_SMEM_FLOATS * 4>>>();
    refine_kernel<<<288, 128>>>(x);
    conv_kernel<<<144, 128, CONV_SMEM_BYTES>>>(w3, b3, w4, b4, out);
}

// round 3
// speedup vs baseline: 2.5513x; 2.5513x over previous
#include <cuda_runtime.h>
#include <cuda_bf16.h>
#include <cstdint>

#define HW    192
#define NPIX  36864
#define CH    64
#define WS    48
#define NTOK  2304
#define NWIN  16
#define TOTTOK 36864

// ---------------- scratch (device globals; no allocations) ----------------
__device__ __align__(16) __nv_bfloat16 g_Qb[NWIN*NTOK*CH];   // [win][n][d]
__device__ __align__(16) __nv_bfloat16 g_Kb[NWIN*NTOK*CH];   // [win][n][d]
__device__ __align__(16) __nv_bfloat16 g_Vb[NWIN*NTOK*CH];   // [win][n][d]
__device__ __align__(16) float g_U [TOTTOK];
__device__ __align__(16) float g_O [TOTTOK*CH];              // [token][d] fp32
__device__ __align__(16) float g_ref[CH*NPIX];
__device__ __align__(16) float g_M [CH*CH];
__device__ __align__(16) float g_b2[CH];

// ---------------- PTX helpers (sm_80-compatible path only) ----------------
__device__ __forceinline__ uint32_t smem_to_u32(const void* p) {
    uint32_t a;
    asm("{ .reg .u64 t; cvta.to.shared.u64 t, %1; cvt.u32.u64 %0, t; }" : "=r"(a) : "l"(p));
    return a;
}

#define CP16(dst, src) \
    asm volatile("cp.async.cg.shared.global [%0], [%1], 16;" :: "r"(dst), "l"(src) : "memory")
#define CP4(dst, src) \
    asm volatile("cp.async.ca.shared.global [%0], [%1], 4;" :: "r"(dst), "l"(src) : "memory")
#define CP_COMMIT() asm volatile("cp.async.commit_group;" ::: "memory")
#define CP_WAIT0()  asm volatile("cp.async.wait_group 0;" ::: "memory")
#define CP_WAIT1()  asm volatile("cp.async.wait_group 1;" ::: "memory")

#define LDSM_X4(r0,r1,r2,r3,addr) \
    asm volatile("ldmatrix.sync.aligned.m8n8.x4.shared.b16 {%0,%1,%2,%3}, [%4];" \
        : "=r"(r0), "=r"(r1), "=r"(r2), "=r"(r3) : "r"(addr))
#define LDSM_X4T(r0,r1,r2,r3,addr) \
    asm volatile("ldmatrix.sync.aligned.m8n8.x4.trans.shared.b16 {%0,%1,%2,%3}, [%4];" \
        : "=r"(r0), "=r"(r1), "=r"(r2), "=r"(r3) : "r"(addr))

#define MMA_BF16(c, a0,a1,a2,a3, b0,b1) \
    asm volatile("mma.sync.aligned.m16n8k16.row.col.f32.bf16.bf16.f32 " \
        "{%0,%1,%2,%3}, {%4,%5,%6,%7}, {%8,%9}, {%0,%1,%2,%3};" \
        : "+f"((c)[0]), "+f"((c)[1]), "+f"((c)[2]), "+f"((c)[3]) \
        : "r"(a0), "r"(a1), "r"(a2), "r"(a3), "r"(b0), "r"(b1))

#define CVT_BF16X2(result, lo, hi) \
    asm("cvt.rn.satfinite.bf16x2.f32 %0, %1, %2;" : "=r"(result) : "f"(hi), "f"(lo))

// ---------------- kernel 1: QKV projections -> bf16 [tok][64] -------------
__global__ void __launch_bounds__(128) qkv_kernel(
    const float* __restrict__ x, const float* __restrict__ rf,
    const float* __restrict__ unc,
    const float* __restrict__ ipw, const float* __restrict__ ipb)
{
    __shared__ float Ws[192*64];
    int tid = threadIdx.x;
    for (int i = tid; i < 192*64; i += 128) Ws[i] = ipw[i];
    __syncthreads();

    int t   = blockIdx.x*128 + tid;
    int win = t / NTOK, n = t % NTOK;
    int pix = ((win>>2)*WS + n/WS)*HW + (win&3)*WS + n%WS;

    float v[64], acc[64];
#pragma unroll
    for (int c = 0; c < 64; c++) v[c] = x[c*NPIX + pix];

    for (int o = 0; o < 64; o++) {
        float a = ipb[o];
        const float4* wp = (const float4*)&Ws[o*64];
#pragma unroll
        for (int k = 0; k < 16; k++) {
            float4 w = wp[k];
            a += v[4*k]*w.x + v[4*k+1]*w.y + v[4*k+2]*w.z + v[4*k+3]*w.w;
        }
        acc[o] = a;
    }
    {
        __nv_bfloat162* qp = (__nv_bfloat162*)(g_Qb + (size_t)t*64);
#pragma unroll
        for (int k = 0; k < 32; k++) qp[k] = __floats2bfloat162_rn(acc[2*k], acc[2*k+1]);
    }

#pragma unroll
    for (int c = 0; c < 64; c++) v[c] = rf[c*NPIX + pix];

    for (int o = 0; o < 64; o++) {
        float a = ipb[64+o];
        const float4* wp = (const float4*)&Ws[(64+o)*64];
#pragma unroll
        for (int k = 0; k < 16; k++) {
            float4 w = wp[k];
            a += v[4*k]*w.x + v[4*k+1]*w.y + v[4*k+2]*w.z + v[4*k+3]*w.w;
        }
        acc[o] = a;
    }
    {
        __nv_bfloat162* kp = (__nv_bfloat162*)(g_Kb + (size_t)t*64);
#pragma unroll
        for (int k = 0; k < 32; k++) kp[k] = __floats2bfloat162_rn(acc[2*k], acc[2*k+1]);
    }

    for (int o = 0; o < 64; o++) {
        float a = ipb[128+o];
        const float4* wp = (const float4*)&Ws[(128+o)*64];
#pragma unroll
        for (int k = 0; k < 16; k++) {
            float4 w = wp[k];
            a += v[4*k]*w.x + v[4*k+1]*w.y + v[4*k+2]*w.z + v[4*k+3]*w.w;
        }
        acc[o] = a;
    }
    {
        __nv_bfloat162* vp = (__nv_bfloat162*)(g_Vb + (size_t)t*64);
#pragma unroll
        for (int k = 0; k < 32; k++) vp[k] = __floats2bfloat162_rn(acc[2*k], acc[2*k+1]);
    }
    g_U[t] = (unc[pix] > 0.01f) ? 1.f : 0.f;
}

// ---------------- kernel 2: warp-MMA flash attention ----------------------
// grid (18 row-tiles, 16 windows), 256 threads = 8 warps, warp = 16 rows.
// No online softmax (bounded logits, fixed max=0): O accumulates across tiles.
#define QOFF   0
#define KOFF   16384
#define VOFF   49152
#define UCOFF  81920
#define ATTN_SMEM (81920 + 1024)

__device__ __forceinline__ void issue_tile(uint32_t smem, int win, int ct, int buf, int tid)
{
    int c0 = ct * 128;
    const char* Kg = (const char*)g_Kb + ((size_t)(win*NTOK + c0))*128;
    const char* Vg = (const char*)g_Vb + ((size_t)(win*NTOK + c0))*128;
    uint32_t kb = smem + KOFF + buf*16384;
    uint32_t vb = smem + VOFF + buf*16384;
#pragma unroll
    for (int i = 0; i < 4; i++) {
        int li = i*256 + tid, r = li >> 3, q = li & 7;
        uint32_t off = r*128 + ((q*16) ^ ((r & 7) << 4));
        CP16(kb + off, Kg + r*128 + q*16);
        CP16(vb + off, Vg + r*128 + q*16);
    }
    if (tid < 128)
        CP4(smem + UCOFF + buf*512 + tid*4, (const char*)(g_U + win*NTOK + c0 + tid));
}

__global__ void __launch_bounds__(256) attn_kernel()
{
    extern __shared__ char smc[];
    uint32_t smem = smem_to_u32(smc);
    int tid = threadIdx.x, wid = tid >> 5, l = tid & 31;
    int win = blockIdx.y, r0 = blockIdx.x * 128;

    // prologue: Q tile + tile 0 via cp.async
    {
        const char* Qg = (const char*)g_Qb + ((size_t)(win*NTOK + r0))*128;
#pragma unroll
        for (int i = 0; i < 4; i++) {
            int li = i*256 + tid, r = li >> 3, q = li & 7;
            CP16(smem + QOFF + r*128 + ((q*16) ^ ((r & 7) << 4)), Qg + r*128 + q*16);
        }
        issue_tile(smem, win, 0, 0, tid);
        CP_COMMIT();
    }

    int row_a = wid*16 + (l >> 2);
    bool urow0 = g_U[win*NTOK + r0 + row_a]     > 0.5f;
    bool urow1 = g_U[win*NTOK + r0 + row_a + 8] > 0.5f;

    CP_WAIT0();
    __syncthreads();

    // Q fragments, persistent across all 18 col tiles
    uint32_t qa[4][4];
    {
        int m = l >> 3;
        int qrow = wid*16 + (m & 1)*8 + (l & 7);
        uint32_t xr = (uint32_t)(l & 7) << 4;
#pragma unroll
        for (int kk = 0; kk < 4; kk++) {
            uint32_t addr = smem + QOFF + qrow*128 + (((uint32_t)(kk*32 + (m >> 1)*16)) ^ xr);
            LDSM_X4(qa[kk][0], qa[kk][1], qa[kk][2], qa[kk][3], addr);
        }
    }

    issue_tile(smem, win, 1, 1, tid);
    CP_COMMIT();

    float o[8][4];
#pragma unroll
    for (int j = 0; j < 8; j++)
#pragma unroll
        for (int c = 0; c < 4; c++) o[j][c] = 0.f;
    float rsum0 = 0.f, rsum1 = 0.f;

    int m = l >> 3;
    uint32_t xr = (uint32_t)(l & 7) << 4;
    int nrow_b = (m >> 1)*8 + (l & 7);      // K ldmatrix row-within-16 block
    int krow_b = (m & 1)*8 + (l & 7);       // V ldmatrix row-within-16 block
    const float* ucsm = (const float*)(smc + UCOFF);

#pragma unroll 1
    for (int ct = 0; ct < 18; ct++) {
        uint32_t kb = smem + KOFF + (ct & 1)*16384;
        uint32_t vb = smem + VOFF + (ct & 1)*16384;

        // ---- S = Q K^T (m16 x n128 x k64 per warp) ----
        float s[16][4];
#pragma unroll
        for (int j = 0; j < 16; j++)
#pragma unroll
            for (int c = 0; c < 4; c++) s[j][c] = 0.f;

#pragma unroll
        for (int kk = 0; kk < 4; kk++) {
            uint32_t cb = ((uint32_t)(kk*32 + (m & 1)*16)) ^ xr;
#pragma unroll
            for (int jb = 0; jb < 8; jb++) {
                uint32_t addr = kb + (16*jb + nrow_b)*128 + cb;
                uint32_t b0, b1, b2, b3;
                LDSM_X4(b0, b1, b2, b3, addr);
                MMA_BF16(s[2*jb],   qa[kk][0], qa[kk][1], qa[kk][2], qa[kk][3], b0, b1);
                MMA_BF16(s[2*jb+1], qa[kk][0], qa[kk][1], qa[kk][2], qa[kk][3], b2, b3);
            }
        }

        // ---- mask + exp + bf16 pack (P reuses accumulator layout) ----
        const float* ucb = ucsm + (ct & 1)*128 + 2*(l & 3);
        uint32_t pc01[16], pc23[16];
#pragma unroll
        for (int j = 0; j < 16; j++) {
            float2 up = *(const float2*)(ucb + 8*j);
            bool c0m = up.x > 0.5f, c1m = up.y > 0.5f;
            float p0 = urow0 ? (c0m ? __expf(0.125f*s[j][0]) : 0.f) : 1.f;
            float p1 = urow0 ? (c1m ? __expf(0.125f*s[j][1]) : 0.f) : 1.f;
            float p2 = urow1 ? (c0m ? __expf(0.125f*s[j][2]) : 0.f) : 1.f;
            float p3 = urow1 ? (c1m ? __expf(0.125f*s[j][3]) : 0.f) : 1.f;
            rsum0 += p0 + p1;
            rsum1 += p2 + p3;
            CVT_BF16X2(pc01[j], p0, p1);
            CVT_BF16X2(pc23[j], p2, p3);
        }

        // ---- O += P V (m16 x n64 x k128 per warp) ----
#pragma unroll
        for (int kc = 0; kc < 8; kc++) {
            uint32_t ra = vb + (16*kc + krow_b)*128;
#pragma unroll
            for (int jb = 0; jb < 4; jb++) {
                uint32_t addr = ra + (((uint32_t)(jb*32 + (m >> 1)*16)) ^ xr);
                uint32_t v0, v1, v2, v3;
                LDSM_X4T(v0, v1, v2, v3, addr);
                MMA_BF16(o[2*jb],   pc01[2*kc], pc23[2*kc], pc01[2*kc+1], pc23[2*kc+1], v0, v1);
                MMA_BF16(o[2*jb+1], pc01[2*kc], pc23[2*kc], pc01[2*kc+1], pc23[2*kc+1], v2, v3);
            }
        }

        __syncthreads();
        if (ct + 2 < 18) { issue_tile(smem, win, ct + 2, ct & 1, tid); CP_COMMIT(); }
        if (ct + 1 < 18) {
            if (ct + 2 < 18) { CP_WAIT1(); } else { CP_WAIT0(); }
            __syncthreads();
        }
    }

    // full row sums across the 4 lanes sharing each row
    rsum0 += __shfl_xor_sync(0xffffffffu, rsum0, 1);
    rsum0 += __shfl_xor_sync(0xffffffffu, rsum0, 2);
    rsum1 += __shfl_xor_sync(0xffffffffu, rsum1, 1);
    rsum1 += __shfl_xor_sync(0xffffffffu, rsum1, 2);
    float inv0 = 1.f / rsum0, inv1 = 1.f / rsum1;

    float* Oa = g_O + ((size_t)(win*NTOK + r0 + row_a))*64 + 2*(l & 3);
    float* Ob = Oa + 8*64;
#pragma unroll
    for (int j = 0; j < 8; j++) {
        *(float2*)(Oa + 8*j) = make_float2(o[j][0]*inv0, o[j][1]*inv0);
        *(float2*)(Ob + 8*j) = make_float2(o[j][2]*inv1, o[j][3]*inv1);
    }
}

// ---------------- prep: M = W1*Wout, b2 = W1*bout + b1 --------------------
__global__ void prep_kernel(const float* __restrict__ w1, const float* __restrict__ b1,
                            const float* __restrict__ wo, const float* __restrict__ bo)
{
    int i = blockIdx.x, j = threadIdx.x;
    float acc = 0.f;
    for (int k = 0; k < 64; k++) acc += w1[i*64+k] * wo[k*64+j];
    g_M[i*64+j] = acc;
    if (j == 0) {
        float a = b1[i];
        for (int k = 0; k < 64; k++) a += w1[i*64+k] * bo[k];
        g_b2[i] = a;
    }
}

// ---------------- kernel 3: refined = x + O*M^T + b2 (NCHW) ---------------
__global__ void __launch_bounds__(256) refine_kernel(const float* __restrict__ x)
{
    __shared__ float Ms[4096];
    __shared__ float bs[64];
    int tid = threadIdx.x;
    for (int i = tid; i < 4096; i += 256) Ms[i] = g_M[i];
    if (tid < 64) bs[tid] = g_b2[tid];
    __syncthreads();

    int gt = blockIdx.x*256 + tid;
    int t = gt >> 2, qq = gt & 3;
    int win = t / NTOK, n = t % NTOK;
    int pix = ((win>>2)*WS + n/WS)*HW + (win&3)*WS + n%WS;

    float ov[64];
    const float4* op = (const float4*)(g_O + (size_t)t*64);
#pragma unroll
    for (int k = 0; k < 16; k++) {
        float4 q = op[k];
        ov[4*k] = q.x; ov[4*k+1] = q.y; ov[4*k+2] = q.z; ov[4*k+3] = q.w;
    }
#pragma unroll
    for (int ci = 0; ci < 16; ci++) {
        int c = qq*16 + ci;
        float acc = bs[c];
        const float4* mp = (const float4*)&Ms[c*64];
#pragma unroll
        for (int k = 0; k < 16; k++) {
            float4 w = mp[k];
            acc += ov[4*k]*w.x + ov[4*k+1]*w.y + ov[4*k+2]*w.z + ov[4*k+3]*w.w;
        }
        g_ref[c*NPIX + pix] = x[c*NPIX + pix] + acc;
    }
}

// ---------------- kernel 4: conv3x3+ReLU, 1x1 head, partition map ---------
#define CONV_SMEM_BYTES ((36864 + 64 + 64) * 4)
__global__ void __launch_bounds__(128) conv_kernel(
    const float* __restrict__ w3, const float* __restrict__ b3,
    const float* __restrict__ w4, const float* __restrict__ b4v,
    float* __restrict__ out)
{
    extern __shared__ float cs[];
    float* Wsm = cs;
    float* b3s = cs + 36864;
    float* w4s = b3s + 64;
    int tid = threadIdx.x;
    for (int i = tid; i < 36864; i += 128) {
        int c = i / 576, r = i % 576, k = r >> 6, o = r & 63;
        Wsm[i] = w3[(o*64 + c)*9 + k];
    }
    if (tid < 64) { b3s[tid] = b3[tid]; w4s[tid] = w4[tid]; }
    __syncthreads();
    float b4 = b4v[0];

    int p0 = blockIdx.x*256 + tid*2;
    int y  = p0 / HW, x0 = p0 % HW;

    float acc0[64], acc1[64];
#pragma unroll
    for (int o = 0; o < 64; o++) { acc0[o] = 0.f; acc1[o] = 0.f; }

    for (int c = 0; c < 64; c++) {
        const float* rp = g_ref + c*NPIX;
        float in[12];
#pragma unroll
        for (int dy = 0; dy < 3; dy++) {
            int yy = y + dy - 1;
            bool yok = (yy >= 0) && (yy < HW);
#pragma unroll
            for (int dx = 0; dx < 4; dx++) {
                int xx = x0 + dx - 1;
                in[dy*4+dx] = (yok && xx >= 0 && xx < HW) ? __ldg(&rp[yy*HW + xx]) : 0.f;
            }
        }
        const float4* wp = (const float4*)&Wsm[c*576];
#pragma unroll
        for (int k = 0; k < 9; k++) {
            int ky = k/3, kx = k%3;
            float i0 = in[ky*4+kx], i1 = in[ky*4+kx+1];
#pragma unroll
            for (int o4 = 0; o4 < 16; o4++) {
                float4 w = wp[k*16 + o4];
                acc0[o4*4+0] += i0*w.x; acc0[o4*4+1] += i0*w.y;
                acc0[o4*4+2] += i0*w.z; acc0[o4*4+3] += i0*w.w;
                acc1[o4*4+0] += i1*w.x; acc1[o4*4+1] += i1*w.y;
                acc1[o4*4+2] += i1*w.z; acc1[o4*4+3] += i1*w.w;
            }
        }
    }

    float s0 = 0.f, s1 = 0.f;
#pragma unroll
    for (int o = 0; o < 64; o++) {
        float r0v = fmaxf(acc0[o] + b3s[o], 0.f);
        float r1v = fmaxf(acc1[o] + b3s[o], 0.f);
        *(float2*)&out[(size_t)o*NPIX + p0] = make_float2(r0v, r1v);
        s0 += r0v * w4s[o]; s1 += r1v * w4s[o];
    }
    *(float2*)&out[(size_t)64*NPIX + p0] = make_float2(s0 + b4, s1 + b4);

    int ry = y % WS;
    bool by = (ry == 0) || (ry == WS-1);
    int rx0 = x0 % WS, rx1 = (x0+1) % WS;
    float pm0 = (by || rx0 == 0 || rx0 == WS-1) ? 0.6f : 1.0f;
    float pm1 = (by || rx1 == 0 || rx1 == WS-1) ? 0.6f : 1.0f;
    *(float2*)&out[(size_t)65*NPIX + p0] = make_float2(pm0, pm1);
}

// ---------------- launch ---------------------------------------------------
extern "C" void kernel_launch(void* const* d_in, const int* in_sizes, int n_in,
                              void* d_out, int out_size)
{
    const float* x    = (const float*)d_in[0];
    const float* rf   = (const float*)d_in[1];
    const float* unc  = (const float*)d_in[2];
    const float* ipw  = (const float*)d_in[3];
    const float* ipb  = (const float*)d_in[4];
    const float* wout = (const float*)d_in[5];
    const float* bout = (const float*)d_in[6];
    const float* w1   = (const float*)d_in[7];
    const float* b1   = (const float*)d_in[8];
    const float* w3   = (const float*)d_in[9];
    const float* b3   = (const float*)d_in[10];
    const float* w4   = (const float*)d_in[11];
    const float* b4   = (const float*)d_in[12];
    float* out = (float*)d_out;

    static bool attr_set = false;
    if (!attr_set) {
        cudaFuncSetAttribute(attn_kernel, cudaFuncAttributeMaxDynamicSharedMemorySize, ATTN_SMEM);
        cudaFuncSetAttribute(conv_kernel, cudaFuncAttributeMaxDynamicSharedMemorySize, CONV_SMEM_BYTES);
        attr_set = true;
    }

    qkv_kernel<<<288, 128>>>(x, rf, unc, ipw, ipb);
    prep_kernel<<<64, 64>>>(w1, b1, wout, bout);
    dim3 ag(18, 16);
    attn_kernel<<<ag, 256, ATTN_SMEM>>>();
    refine_kernel<<<576, 256>>>(x);
    conv_kernel<<<144, 128, CONV_SMEM_BYTES>>>(w3, b3, w4, b4, out);
}

// round 4
// speedup vs baseline: 4.8671x; 1.9077x over previous
#include <cuda_runtime.h>
#include <cuda_bf16.h>
#include <cstdint>

#define HW    192
#define NPIX  36864
#define CH    64
#define WS    48
#define NTOK  2304
#define NWIN  16
#define TOTTOK 36864

// ---------------- scratch (device globals; no allocations) ----------------
__device__ __align__(16) __nv_bfloat16 g_Qb[NWIN*NTOK*CH];   // [win][n][d]
__device__ __align__(16) __nv_bfloat16 g_Kb[NWIN*NTOK*CH];   // [win][n][d]
__device__ __align__(16) __nv_bfloat16 g_Vb[NWIN*NTOK*CH];   // [win][n][d]
__device__ __align__(16) float g_U [TOTTOK];
__device__ __align__(16) float g_ref[CH*NPIX];               // NCHW refined
__device__ __align__(16) __nv_bfloat16 g_Mb[CH*CH];          // fused W1*Wout, bf16 [c][d]
__device__ __align__(16) float g_b2[CH];
__device__ __align__(16) float g_W3t[CH*9*CH];               // [c][tap][o] fp32

// ---------------- PTX helpers (sm_80-compatible path only) ----------------
__device__ __forceinline__ uint32_t smem_to_u32(const void* p) {
    uint32_t a;
    asm("{ .reg .u64 t; cvta.to.shared.u64 t, %1; cvt.u32.u64 %0, t; }" : "=r"(a) : "l"(p));
    return a;
}

#define CP16(dst, src) \
    asm volatile("cp.async.cg.shared.global [%0], [%1], 16;" :: "r"(dst), "l"(src) : "memory")
#define CP4(dst, src) \
    asm volatile("cp.async.ca.shared.global [%0], [%1], 4;" :: "r"(dst), "l"(src) : "memory")
#define CP_COMMIT() asm volatile("cp.async.commit_group;" ::: "memory")
#define CP_WAIT0()  asm volatile("cp.async.wait_group 0;" ::: "memory")
#define CP_WAIT1()  asm volatile("cp.async.wait_group 1;" ::: "memory")

#define LDSM_X4(r0,r1,r2,r3,addr) \
    asm volatile("ldmatrix.sync.aligned.m8n8.x4.shared.b16 {%0,%1,%2,%3}, [%4];" \
        : "=r"(r0), "=r"(r1), "=r"(r2), "=r"(r3) : "r"(addr))
#define LDSM_X4T(r0,r1,r2,r3,addr) \
    asm volatile("ldmatrix.sync.aligned.m8n8.x4.trans.shared.b16 {%0,%1,%2,%3}, [%4];" \
        : "=r"(r0), "=r"(r1), "=r"(r2), "=r"(r3) : "r"(addr))

#define MMA_BF16(c, a0,a1,a2,a3, b0,b1) \
    asm volatile("mma.sync.aligned.m16n8k16.row.col.f32.bf16.bf16.f32 " \
        "{%0,%1,%2,%3}, {%4,%5,%6,%7}, {%8,%9}, {%0,%1,%2,%3};" \
        : "+f"((c)[0]), "+f"((c)[1]), "+f"((c)[2]), "+f"((c)[3]) \
        : "r"(a0), "r"(a1), "r"(a2), "r"(a3), "r"(b0), "r"(b1))

#define MMA_TF32(c, a0,a1,a2,a3, b0,b1) \
    asm volatile("mma.sync.aligned.m16n8k8.row.col.f32.tf32.tf32.f32 " \
        "{%0,%1,%2,%3}, {%4,%5,%6,%7}, {%8,%9}, {%0,%1,%2,%3};" \
        : "+f"((c)[0]), "+f"((c)[1]), "+f"((c)[2]), "+f"((c)[3]) \
        : "r"(a0), "r"(a1), "r"(a2), "r"(a3), "r"(b0), "r"(b1))

#define CVT_BF16X2(result, lo, hi) \
    asm("cvt.rn.satfinite.bf16x2.f32 %0, %1, %2;" : "=r"(result) : "f"(hi), "f"(lo))

// ---------------- kernel 1: QKV projections -> bf16 [tok][64] -------------
__global__ void __launch_bounds__(128) qkv_kernel(
    const float* __restrict__ x, const float* __restrict__ rf,
    const float* __restrict__ unc,
    const float* __restrict__ ipw, const float* __restrict__ ipb)
{
    __shared__ float Ws[192*64];
    int tid = threadIdx.x;
    for (int i = tid; i < 192*64; i += 128) Ws[i] = ipw[i];
    __syncthreads();

    int t   = blockIdx.x*128 + tid;
    int win = t / NTOK, n = t % NTOK;
    int pix = ((win>>2)*WS + n/WS)*HW + (win&3)*WS + n%WS;

    float v[64], acc[64];
#pragma unroll
    for (int c = 0; c < 64; c++) v[c] = x[c*NPIX + pix];

    for (int o = 0; o < 64; o++) {
        float a = ipb[o];
        const float4* wp = (const float4*)&Ws[o*64];
#pragma unroll
        for (int k = 0; k < 16; k++) {
            float4 w = wp[k];
            a += v[4*k]*w.x + v[4*k+1]*w.y + v[4*k+2]*w.z + v[4*k+3]*w.w;
        }
        acc[o] = a;
    }
    {
        __nv_bfloat162* qp = (__nv_bfloat162*)(g_Qb + (size_t)t*64);
#pragma unroll
        for (int k = 0; k < 32; k++) qp[k] = __floats2bfloat162_rn(acc[2*k], acc[2*k+1]);
    }

#pragma unroll
    for (int c = 0; c < 64; c++) v[c] = rf[c*NPIX + pix];

    for (int o = 0; o < 64; o++) {
        float a = ipb[64+o];
        const float4* wp = (const float4*)&Ws[(64+o)*64];
#pragma unroll
        for (int k = 0; k < 16; k++) {
            float4 w = wp[k];
            a += v[4*k]*w.x + v[4*k+1]*w.y + v[4*k+2]*w.z + v[4*k+3]*w.w;
        }
        acc[o] = a;
    }
    {
        __nv_bfloat162* kp = (__nv_bfloat162*)(g_Kb + (size_t)t*64);
#pragma unroll
        for (int k = 0; k < 32; k++) kp[k] = __floats2bfloat162_rn(acc[2*k], acc[2*k+1]);
    }

    for (int o = 0; o < 64; o++) {
        float a = ipb[128+o];
        const float4* wp = (const float4*)&Ws[(128+o)*64];
#pragma unroll
        for (int k = 0; k < 16; k++) {
            float4 w = wp[k];
            a += v[4*k]*w.x + v[4*k+1]*w.y + v[4*k+2]*w.z + v[4*k+3]*w.w;
        }
        acc[o] = a;
    }
    {
        __nv_bfloat162* vp = (__nv_bfloat162*)(g_Vb + (size_t)t*64);
#pragma unroll
        for (int k = 0; k < 32; k++) vp[k] = __floats2bfloat162_rn(acc[2*k], acc[2*k+1]);
    }
    g_U[t] = (unc[pix] > 0.01f) ? 1.f : 0.f;
}

// ---------------- prep: M=W1*Wout (bf16), b2, w3 transpose ---------------
__global__ void prep_kernel(const float* __restrict__ w1, const float* __restrict__ b1,
                            const float* __restrict__ wo, const float* __restrict__ bo,
                            const float* __restrict__ w3)
{
    int i = blockIdx.x, j = threadIdx.x;
    float acc = 0.f;
    for (int k = 0; k < 64; k++) acc += w1[i*64+k] * wo[k*64+j];
    g_Mb[i*64+j] = __float2bfloat16_rn(acc);
    if (j == 0) {
        float a = b1[i];
        for (int k = 0; k < 64; k++) a += w1[i*64+k] * bo[k];
        g_b2[i] = a;
    }
    // g_W3t[(c*9+tap)*64 + o] = w3[o][c][tap] ; c=i, o=j
#pragma unroll
    for (int tap = 0; tap < 9; tap++)
        g_W3t[(i*9 + tap)*64 + j] = w3[(j*64 + i)*9 + tap];
}

// ---------------- kernel 2: warp-MMA flash attention + fused refine -------
// grid (18 row-tiles, 16 windows), 256 threads = 8 warps, warp = 16 rows.
#define QOFF   0
#define KOFF   16384
#define VOFF   49152
#define UCOFF  81920
#define ATTN_SMEM (81920 + 1024)

__device__ __forceinline__ void issue_tile(uint32_t smem, int win, int ct, int buf, int tid)
{
    int c0 = ct * 128;
    const char* Kg = (const char*)g_Kb + ((size_t)(win*NTOK + c0))*128;
    const char* Vg = (const char*)g_Vb + ((size_t)(win*NTOK + c0))*128;
    uint32_t kb = smem + KOFF + buf*16384;
    uint32_t vb = smem + VOFF + buf*16384;
#pragma unroll
    for (int i = 0; i < 4; i++) {
        int li = i*256 + tid, r = li >> 3, q = li & 7;
        uint32_t off = r*128 + ((q*16) ^ ((r & 7) << 4));
        CP16(kb + off, Kg + r*128 + q*16);
        CP16(vb + off, Vg + r*128 + q*16);
    }
    if (tid < 128)
        CP4(smem + UCOFF + buf*512 + tid*4, (const char*)(g_U + win*NTOK + c0 + tid));
}

__global__ void __launch_bounds__(256) attn_kernel(const float* __restrict__ x)
{
    extern __shared__ char smc[];
    uint32_t smem = smem_to_u32(smc);
    int tid = threadIdx.x, wid = tid >> 5, l = tid & 31;
    int win = blockIdx.y, r0 = blockIdx.x * 128;

    // prologue: Q tile + tile 0 via cp.async
    {
        const char* Qg = (const char*)g_Qb + ((size_t)(win*NTOK + r0))*128;
#pragma unroll
        for (int i = 0; i < 4; i++) {
            int li = i*256 + tid, r = li >> 3, q = li & 7;
            CP16(smem + QOFF + r*128 + ((q*16) ^ ((r & 7) << 4)), Qg + r*128 + q*16);
        }
        issue_tile(smem, win, 0, 0, tid);
        CP_COMMIT();
    }

    int row_a = wid*16 + (l >> 2);
    bool urow0 = g_U[win*NTOK + r0 + row_a]     > 0.5f;
    bool urow1 = g_U[win*NTOK + r0 + row_a + 8] > 0.5f;

    CP_WAIT0();
    __syncthreads();

    // Q fragments, persistent across all 18 col tiles
    uint32_t qa[4][4];
    {
        int m = l >> 3;
        int qrow = wid*16 + (m & 1)*8 + (l & 7);
        uint32_t xr = (uint32_t)(l & 7) << 4;
#pragma unroll
        for (int kk = 0; kk < 4; kk++) {
            uint32_t addr = smem + QOFF + qrow*128 + (((uint32_t)(kk*32 + (m >> 1)*16)) ^ xr);
            LDSM_X4(qa[kk][0], qa[kk][1], qa[kk][2], qa[kk][3], addr);
        }
    }

    issue_tile(smem, win, 1, 1, tid);
    CP_COMMIT();

    float o[8][4];
#pragma unroll
    for (int j = 0; j < 8; j++)
#pragma unroll
        for (int c = 0; c < 4; c++) o[j][c] = 0.f;
    float rsum0 = 0.f, rsum1 = 0.f;

    int m = l >> 3;
    uint32_t xr = (uint32_t)(l & 7) << 4;
    int nrow_b = (m >> 1)*8 + (l & 7);
    int krow_b = (m & 1)*8 + (l & 7);
    const float* ucsm = (const float*)(smc + UCOFF);

#pragma unroll 1
    for (int ct = 0; ct < 18; ct++) {
        uint32_t kb = smem + KOFF + (ct & 1)*16384;
        uint32_t vb = smem + VOFF + (ct & 1)*16384;

        float s[16][4];
#pragma unroll
        for (int j = 0; j < 16; j++)
#pragma unroll
            for (int c = 0; c < 4; c++) s[j][c] = 0.f;

#pragma unroll
        for (int kk = 0; kk < 4; kk++) {
            uint32_t cb = ((uint32_t)(kk*32 + (m & 1)*16)) ^ xr;
#pragma unroll
            for (int jb = 0; jb < 8; jb++) {
                uint32_t addr = kb + (16*jb + nrow_b)*128 + cb;
                uint32_t b0, b1, b2, b3;
                LDSM_X4(b0, b1, b2, b3, addr);
                MMA_BF16(s[2*jb],   qa[kk][0], qa[kk][1], qa[kk][2], qa[kk][3], b0, b1);
                MMA_BF16(s[2*jb+1], qa[kk][0], qa[kk][1], qa[kk][2], qa[kk][3], b2, b3);
            }
        }

        const float* ucb = ucsm + (ct & 1)*128 + 2*(l & 3);
        uint32_t pc01[16], pc23[16];
#pragma unroll
        for (int j = 0; j < 16; j++) {
            float2 up = *(const float2*)(ucb + 8*j);
            bool c0m = up.x > 0.5f, c1m = up.y > 0.5f;
            float p0 = urow0 ? (c0m ? __expf(0.125f*s[j][0]) : 0.f) : 1.f;
            float p1 = urow0 ? (c1m ? __expf(0.125f*s[j][1]) : 0.f) : 1.f;
            float p2 = urow1 ? (c0m ? __expf(0.125f*s[j][2]) : 0.f) : 1.f;
            float p3 = urow1 ? (c1m ? __expf(0.125f*s[j][3]) : 0.f) : 1.f;
            rsum0 += p0 + p1;
            rsum1 += p2 + p3;
            CVT_BF16X2(pc01[j], p0, p1);
            CVT_BF16X2(pc23[j], p2, p3);
        }

#pragma unroll
        for (int kc = 0; kc < 8; kc++) {
            uint32_t ra = vb + (16*kc + krow_b)*128;
#pragma unroll
            for (int jb = 0; jb < 4; jb++) {
                uint32_t addr = ra + (((uint32_t)(jb*32 + (m >> 1)*16)) ^ xr);
                uint32_t v0, v1, v2, v3;
                LDSM_X4T(v0, v1, v2, v3, addr);
                MMA_BF16(o[2*jb],   pc01[2*kc], pc23[2*kc], pc01[2*kc+1], pc23[2*kc+1], v0, v1);
                MMA_BF16(o[2*jb+1], pc01[2*kc], pc23[2*kc], pc01[2*kc+1], pc23[2*kc+1], v2, v3);
            }
        }

        __syncthreads();
        if (ct + 2 < 18) { issue_tile(smem, win, ct + 2, ct & 1, tid); CP_COMMIT(); }
        if (ct + 1 < 18) {
            if (ct + 2 < 18) { CP_WAIT1(); } else { CP_WAIT0(); }
            __syncthreads();
        }
    }

    rsum0 += __shfl_xor_sync(0xffffffffu, rsum0, 1);
    rsum0 += __shfl_xor_sync(0xffffffffu, rsum0, 2);
    rsum1 += __shfl_xor_sync(0xffffffffu, rsum1, 1);
    rsum1 += __shfl_xor_sync(0xffffffffu, rsum1, 2);
    float inv0 = 1.f / rsum0, inv1 = 1.f / rsum1;

    // ---- fused refine: refined = x + (O/rsum)*M^T + b2 ----
    // load M tile (64x64 bf16) into QOFF area, swizzled like K
    __syncthreads();
    {
        const char* Mg = (const char*)g_Mb;
#pragma unroll
        for (int i = 0; i < 2; i++) {
            int li = i*256 + tid, r = li >> 3, q = li & 7;
            CP16(smem + QOFF + r*128 + ((q*16) ^ ((r & 7) << 4)), Mg + r*128 + q*16);
        }
        CP_COMMIT(); CP_WAIT0();
    }
    __syncthreads();

    // A fragments = normalized O in bf16 (accumulator layout == A layout)
    uint32_t af[4][4];
#pragma unroll
    for (int kk = 0; kk < 4; kk++) {
        CVT_BF16X2(af[kk][0], o[2*kk][0]*inv0,   o[2*kk][1]*inv0);
        CVT_BF16X2(af[kk][1], o[2*kk][2]*inv1,   o[2*kk][3]*inv1);
        CVT_BF16X2(af[kk][2], o[2*kk+1][0]*inv0, o[2*kk+1][1]*inv0);
        CVT_BF16X2(af[kk][3], o[2*kk+1][2]*inv1, o[2*kk+1][3]*inv1);
    }

    float dd[8][4];
#pragma unroll
    for (int j = 0; j < 8; j++)
#pragma unroll
        for (int c = 0; c < 4; c++) dd[j][c] = 0.f;

#pragma unroll
    for (int kk = 0; kk < 4; kk++) {
        uint32_t cb = ((uint32_t)(kk*32 + (m & 1)*16)) ^ xr;
#pragma unroll
        for (int jb = 0; jb < 4; jb++) {
            uint32_t addr = smem + QOFF + (16*jb + nrow_b)*128 + cb;
            uint32_t b0, b1, b2, b3;
            LDSM_X4(b0, b1, b2, b3, addr);
            MMA_BF16(dd[2*jb],   af[kk][0], af[kk][1], af[kk][2], af[kk][3], b0, b1);
            MMA_BF16(dd[2*jb+1], af[kk][0], af[kk][1], af[kk][2], af[kk][3], b2, b3);
        }
    }

    // write refined (NCHW) with x add + b2
    int n0 = r0 + row_a;
    int n1 = n0 + 8;
    int px0 = ((win>>2)*WS + n0/WS)*HW + (win&3)*WS + n0%WS;
    int px1 = ((win>>2)*WS + n1/WS)*HW + (win&3)*WS + n1%WS;
#pragma unroll
    for (int jb = 0; jb < 4; jb++) {
#pragma unroll
        for (int hh = 0; hh < 2; hh++) {
            int c = 16*jb + 8*hh + 2*(l & 3);
            int j = 2*jb + hh;
            float2 b2v = *(const float2*)(g_b2 + c);
            g_ref[(size_t)c*NPIX + px0]     = x[(size_t)c*NPIX + px0]     + dd[j][0] + b2v.x;
            g_ref[(size_t)(c+1)*NPIX + px0] = x[(size_t)(c+1)*NPIX + px0] + dd[j][1] + b2v.y;
            g_ref[(size_t)c*NPIX + px1]     = x[(size_t)c*NPIX + px1]     + dd[j][2] + b2v.x;
            g_ref[(size_t)(c+1)*NPIX + px1] = x[(size_t)(c+1)*NPIX + px1] + dd[j][3] + b2v.y;
        }
    }
}

// ---------------- kernel 3: conv3x3 via tf32 implicit GEMM ----------------
// block = 8 rows x 32 cols of pixels, 256 threads = 8 warps (1 image row each)
__global__ void __launch_bounds__(256) conv_kernel(
    const float* __restrict__ b3, const float* __restrict__ w4,
    const float* __restrict__ b4v, float* __restrict__ out)
{
    __shared__ float in_t[8*408];      // 8 ch planes, 10x40 (+8 pad)
    __shared__ float wt[9*8*72];       // [tap][k][n] k-stride 72
    __shared__ float b3s[64], w4s[64];

    int tid = threadIdx.x, wid = tid >> 5, l = tid & 31;
    int cx0 = blockIdx.x*32, y0 = blockIdx.y*8;
    if (tid < 64) { b3s[tid] = b3[tid]; w4s[tid] = w4[tid]; }

    float acc[2][8][4];
#pragma unroll
    for (int mb = 0; mb < 2; mb++)
#pragma unroll
        for (int nb = 0; nb < 8; nb++)
#pragma unroll
            for (int c = 0; c < 4; c++) acc[mb][nb][c] = 0.f;

    for (int kc = 0; kc < 8; kc++) {
        __syncthreads();
        // input tile: 8 ch x 10 rows x 34 cols, zero-padded borders
        for (int idx = tid; idx < 2720; idx += 256) {
            int ci = idx / 340, rem = idx % 340, ry = rem / 34, rcx = rem % 34;
            int gy = y0 - 1 + ry, gx = cx0 - 1 + rcx;
            float v = 0.f;
            if (gy >= 0 && gy < HW && gx >= 0 && gx < HW)
                v = g_ref[(size_t)(kc*8 + ci)*NPIX + gy*HW + gx];
            in_t[ci*408 + ry*40 + rcx] = v;
        }
        // weights for this k-chunk: wt[(tap*8+k)*72+n] = g_W3t[kc*4608 + (k*9+tap)*64 + n]
        const float* wsrc = g_W3t + kc*4608;
        for (int idx = tid; idx < 4608; idx += 256) {
            int k = idx / 576, tap = (idx >> 6) % 9, n = idx & 63;
            wt[(tap*8 + k)*72 + n] = wsrc[idx];
        }
        __syncthreads();

#pragma unroll
        for (int tap = 0; tap < 9; tap++) {
            const int dyv = tap / 3, dxv = tap % 3;
            const float* wb = wt + tap*576;
            uint32_t b0a[8], b1a[8];
#pragma unroll
            for (int nb = 0; nb < 8; nb++) {
                b0a[nb] = __float_as_uint(wb[(l & 3)*72 + (l >> 2) + 8*nb]);
                b1a[nb] = __float_as_uint(wb[((l & 3) + 4)*72 + (l >> 2) + 8*nb]);
            }
            int rowoff = (wid + dyv)*40 + dxv;
#pragma unroll
            for (int mb = 0; mb < 2; mb++) {
                int cb = 16*mb + (l >> 2) + rowoff;
                uint32_t a0 = __float_as_uint(in_t[(l & 3)*408 + cb]);
                uint32_t a1 = __float_as_uint(in_t[(l & 3)*408 + cb + 8]);
                uint32_t a2 = __float_as_uint(in_t[((l & 3) + 4)*408 + cb]);
                uint32_t a3 = __float_as_uint(in_t[((l & 3) + 4)*408 + cb + 8]);
#pragma unroll
                for (int nb = 0; nb < 8; nb++)
                    MMA_TF32(acc[mb][nb], a0, a1, a2, a3, b0a[nb], b1a[nb]);
            }
        }
    }

    // epilogue: bias+relu, r3 store, 1x1 head, partition map
    int y = y0 + wid;
    float b4 = b4v[0];
    float s[2][2] = {{0.f, 0.f}, {0.f, 0.f}};
#pragma unroll
    for (int mb = 0; mb < 2; mb++) {
        int x1 = cx0 + 16*mb + (l >> 2);
        int x2 = x1 + 8;
#pragma unroll
        for (int nb = 0; nb < 8; nb++) {
            int oc = 8*nb + 2*(l & 3);
            float r00 = fmaxf(acc[mb][nb][0] + b3s[oc],   0.f);
            float r01 = fmaxf(acc[mb][nb][1] + b3s[oc+1], 0.f);
            float r10 = fmaxf(acc[mb][nb][2] + b3s[oc],   0.f);
            float r11 = fmaxf(acc[mb][nb][3] + b3s[oc+1], 0.f);
            out[(size_t)oc*NPIX     + y*HW + x1] = r00;
            out[(size_t)(oc+1)*NPIX + y*HW + x1] = r01;
            out[(size_t)oc*NPIX     + y*HW + x2] = r10;
            out[(size_t)(oc+1)*NPIX + y*HW + x2] = r11;
            s[mb][0] += r00*w4s[oc] + r01*w4s[oc+1];
            s[mb][1] += r10*w4s[oc] + r11*w4s[oc+1];
        }
    }
#pragma unroll
    for (int mb = 0; mb < 2; mb++) {
#pragma unroll
        for (int h = 0; h < 2; h++) {
            s[mb][h] += __shfl_xor_sync(0xffffffffu, s[mb][h], 1);
            s[mb][h] += __shfl_xor_sync(0xffffffffu, s[mb][h], 2);
        }
    }
    if ((l & 3) == 0) {
#pragma unroll
        for (int mb = 0; mb < 2; mb++) {
            int x1 = cx0 + 16*mb + (l >> 2);
            out[(size_t)64*NPIX + y*HW + x1]     = s[mb][0] + b4;
            out[(size_t)64*NPIX + y*HW + x1 + 8] = s[mb][1] + b4;
        }
    }
    // partition map: 256 px per block, 1 per thread
    {
        int yy = y0 + (tid >> 5), xx = cx0 + (tid & 31);
        int ry = yy % WS, rx = xx % WS;
        float pm = ((ry == 0) | (ry == WS-1) | (rx == 0) | (rx == WS-1)) ? 0.6f : 1.0f;
        out[(size_t)65*NPIX + yy*HW + xx] = pm;
    }
}

// ---------------- launch ---------------------------------------------------
extern "C" void kernel_launch(void* const* d_in, const int* in_sizes, int n_in,
                              void* d_out, int out_size)
{
    const float* x    = (const float*)d_in[0];
    const float* rf   = (const float*)d_in[1];
    const float* unc  = (const float*)d_in[2];
    const float* ipw  = (const float*)d_in[3];
    const float* ipb  = (const float*)d_in[4];
    const float* wout = (const float*)d_in[5];
    const float* bout = (const float*)d_in[6];
    const float* w1   = (const float*)d_in[7];
    const float* b1   = (const float*)d_in[8];
    const float* w3   = (const float*)d_in[9];
    const float* b3   = (const float*)d_in[10];
    const float* w4   = (const float*)d_in[11];
    const float* b4   = (const float*)d_in[12];
    float* out = (float*)d_out;

    static bool attr_set = false;
    if (!attr_set) {
        cudaFuncSetAttribute(attn_kernel, cudaFuncAttributeMaxDynamicSharedMemorySize, ATTN_SMEM);
        attr_set = true;
    }

    qkv_kernel<<<288, 128>>>(x, rf, unc, ipw, ipb);
    prep_kernel<<<64, 64>>>(w1, b1, wout, bout, w3);
    dim3 ag(18, 16);
    attn_kernel<<<ag, 256, ATTN_SMEM>>>(x);
    dim3 cg(6, 24);
    conv_kernel<<<cg, 256>>>(b3, w4, b4, out);
}

// round 5
// speedup vs baseline: 7.5251x; 1.5461x over previous
#include <cuda_runtime.h>
#include <cuda_bf16.h>
#include <cstdint>

#define HW    192
#define NPIX  36864
#define CH    64
#define WS    48
#define NTOK  2304
#define NWIN  16
#define TOTTOK 36864

// ---------------- scratch (device globals; no allocations) ----------------
__device__ __align__(16) __nv_bfloat16 g_Qb[NWIN*NTOK*CH];   // [win][n][d]
__device__ __align__(16) __nv_bfloat16 g_Kb[NWIN*NTOK*CH];   // [win][n][d]
__device__ __align__(16) __nv_bfloat16 g_Vb[NWIN*NTOK*CH];   // [win][n][d]
__device__ __align__(16) float g_U [TOTTOK];                 // 0 = active, -150 = masked
__device__ __align__(16) float g_ref[CH*NPIX];               // NCHW refined
__device__ __align__(16) __nv_bfloat16 g_Mb[CH*CH];          // fused W1*Wout, bf16 [c][d]
__device__ __align__(16) float g_b2[CH];
__device__ __align__(16) float g_W3t[CH*9*CH];               // [c][tap][o] tf32-rounded
__device__ __align__(16) __nv_bfloat16 g_Wib[192*CH];        // in_proj bf16 [o][c]

// ---------------- PTX helpers ----------------------------------------------
__device__ __forceinline__ uint32_t smem_to_u32(const void* p) {
    uint32_t a;
    asm("{ .reg .u64 t; cvta.to.shared.u64 t, %1; cvt.u32.u64 %0, t; }" : "=r"(a) : "l"(p));
    return a;
}
__device__ __forceinline__ uint32_t tf32r(float v) {
    uint32_t r; asm("cvt.rna.tf32.f32 %0, %1;" : "=r"(r) : "f"(v)); return r;
}

#define CP16(dst, src) \
    asm volatile("cp.async.cg.shared.global [%0], [%1], 16;" :: "r"(dst), "l"(src) : "memory")
#define CP4(dst, src) \
    asm volatile("cp.async.ca.shared.global [%0], [%1], 4;" :: "r"(dst), "l"(src) : "memory")
#define CPZ(dst, src, n) \
    asm volatile("cp.async.ca.shared.global [%0], [%1], 4, %2;" :: "r"(dst), "l"(src), "r"(n) : "memory")
#define CP_COMMIT() asm volatile("cp.async.commit_group;" ::: "memory")
#define CP_WAIT0()  asm volatile("cp.async.wait_group 0;" ::: "memory")
#define CP_WAIT1()  asm volatile("cp.async.wait_group 1;" ::: "memory")

#define LDSM_X4(r0,r1,r2,r3,addr) \
    asm volatile("ldmatrix.sync.aligned.m8n8.x4.shared.b16 {%0,%1,%2,%3}, [%4];" \
        : "=r"(r0), "=r"(r1), "=r"(r2), "=r"(r3) : "r"(addr))
#define LDSM_X4T(r0,r1,r2,r3,addr) \
    asm volatile("ldmatrix.sync.aligned.m8n8.x4.trans.shared.b16 {%0,%1,%2,%3}, [%4];" \
        : "=r"(r0), "=r"(r1), "=r"(r2), "=r"(r3) : "r"(addr))

#define MMA_BF16(c, a0,a1,a2,a3, b0,b1) \
    asm volatile("mma.sync.aligned.m16n8k16.row.col.f32.bf16.bf16.f32 " \
        "{%0,%1,%2,%3}, {%4,%5,%6,%7}, {%8,%9}, {%0,%1,%2,%3};" \
        : "+f"((c)[0]), "+f"((c)[1]), "+f"((c)[2]), "+f"((c)[3]) \
        : "r"(a0), "r"(a1), "r"(a2), "r"(a3), "r"(b0), "r"(b1))

#define MMA_TF32(c, a0,a1,a2,a3, b0,b1) \
    asm volatile("mma.sync.aligned.m16n8k8.row.col.f32.tf32.tf32.f32 " \
        "{%0,%1,%2,%3}, {%4,%5,%6,%7}, {%8,%9}, {%0,%1,%2,%3};" \
        : "+f"((c)[0]), "+f"((c)[1]), "+f"((c)[2]), "+f"((c)[3]) \
        : "r"(a0), "r"(a1), "r"(a2), "r"(a3), "r"(b0), "r"(b1))

#define CVT_BF16X2(result, lo, hi) \
    asm("cvt.rn.satfinite.bf16x2.f32 %0, %1, %2;" : "=r"(result) : "f"(hi), "f"(lo))
#define EX2F(r, x) asm("ex2.approx.ftz.f32 %0, %1;" : "=f"(r) : "f"(x))

// ---------------- prep: weights preprocessing ------------------------------
__global__ void prep_kernel(const float* __restrict__ w1, const float* __restrict__ b1,
                            const float* __restrict__ wo, const float* __restrict__ bo,
                            const float* __restrict__ w3, const float* __restrict__ ipw)
{
    int i = blockIdx.x, j = threadIdx.x;
    float acc = 0.f;
    for (int k = 0; k < 64; k++) acc += w1[i*64+k] * wo[k*64+j];
    g_Mb[i*64+j] = __float2bfloat16_rn(acc);
    if (j == 0) {
        float a = b1[i];
        for (int k = 0; k < 64; k++) a += w1[i*64+k] * bo[k];
        g_b2[i] = a;
    }
#pragma unroll
    for (int tap = 0; tap < 9; tap++)
        g_W3t[(i*9 + tap)*64 + j] = __uint_as_float(tf32r(w3[(j*64 + i)*9 + tap]));
#pragma unroll
    for (int s = 0; s < 3; s++) {
        int o = s*64 + i;
        g_Wib[o*64 + j] = __float2bfloat16_rn(ipw[o*64 + j]);
    }
}

// ---------------- kernel 1: QKV projections via bf16 MMA -------------------
// 288 blocks x 256 threads; block = 128 tokens; warp = 16 token rows.
#define XS_STRIDE 132
#define QKV_SMEM ((2*64*XS_STRIDE + 192*36 + 192)*4)
__global__ void __launch_bounds__(256) qkv_kernel(
    const float* __restrict__ x, const float* __restrict__ rf,
    const float* __restrict__ unc, const float* __restrict__ ipb)
{
    extern __shared__ float qsm[];
    float* Xs = qsm;                          // [64][132]
    float* Rs = qsm + 64*XS_STRIDE;           // [64][132]
    uint32_t* Wsb = (uint32_t*)(qsm + 2*64*XS_STRIDE);  // [192][36] words (bf16x2)
    float* bs = qsm + 2*64*XS_STRIDE + 192*36;          // [192]
    uint32_t smem = smem_to_u32(qsm);

    int tid = threadIdx.x, wid = tid >> 5, l = tid & 31;
    int t0  = blockIdx.x * 128;
    int win = blockIdx.x / 18;
    int nbase = (blockIdx.x % 18) * 128;
    int pixbase = (win >> 2)*WS*HW + (win & 3)*WS;

    // stage X, RF (fp32), W (bf16 pairs), bias via cp.async
#pragma unroll
    for (int it = 0; it < 32; it++) {
        int idx = it*256 + tid;
        int c = idx >> 7, tok = idx & 127;
        int n = nbase + tok;
        int pix = pixbase + (n/WS)*HW + (n%WS);
        CP4(smem + (c*XS_STRIDE + tok)*4, x  + c*NPIX + pix);
        CP4(smem + ((64 + c)*XS_STRIDE + tok)*4, rf + c*NPIX + pix);
    }
    {
        uint32_t wbase = smem + (2*64*XS_STRIDE)*4;
#pragma unroll
        for (int i = tid; i < 1536; i += 256) {
            int o = i >> 3, w4 = i & 7;
            CP16(wbase + (o*36 + w4*4)*4, g_Wib + o*64 + w4*8);
        }
        if (tid < 192) CP4(smem + (2*64*XS_STRIDE + 192*36 + tid)*4, ipb + tid);
    }
    CP_COMMIT();

    if (tid < 128) {
        int n = nbase + tid;
        int pix = pixbase + (n/WS)*HW + (n%WS);
        g_U[t0 + tid] = (unc[pix] > 0.01f) ? 0.f : -150.f;
    }

    CP_WAIT0();
    __syncthreads();

    int r = wid*16 + (l >> 2);
    // build A fragments from fp32 smem (x and rf)
    uint32_t ax[4][4], ar[4][4];
#pragma unroll
    for (int kk = 0; kk < 4; kk++) {
        int k0 = kk*16 + 2*(l & 3);
#pragma unroll
        for (int half = 0; half < 2; half++) {
            int k = k0 + half*8;
            CVT_BF16X2(ax[kk][2*half],   Xs[k*XS_STRIDE + r],     Xs[(k+1)*XS_STRIDE + r]);
            CVT_BF16X2(ax[kk][2*half+1], Xs[k*XS_STRIDE + r + 8], Xs[(k+1)*XS_STRIDE + r + 8]);
            CVT_BF16X2(ar[kk][2*half],   Rs[k*XS_STRIDE + r],     Rs[(k+1)*XS_STRIDE + r]);
            CVT_BF16X2(ar[kk][2*half+1], Rs[k*XS_STRIDE + r + 8], Rs[(k+1)*XS_STRIDE + r + 8]);
        }
    }

#pragma unroll
    for (int seg = 0; seg < 3; seg++) {
        float acc[8][4];
#pragma unroll
        for (int nb = 0; nb < 8; nb++)
#pragma unroll
            for (int c = 0; c < 4; c++) acc[nb][c] = 0.f;

#pragma unroll
        for (int nb = 0; nb < 8; nb++) {
            int o = seg*64 + nb*8 + (l >> 2);
#pragma unroll
            for (int kk = 0; kk < 4; kk++) {
                uint32_t b0 = Wsb[o*36 + kk*8 + (l & 3)];
                uint32_t b1 = Wsb[o*36 + kk*8 + (l & 3) + 4];
                if (seg == 0) MMA_BF16(acc[nb], ax[kk][0], ax[kk][1], ax[kk][2], ax[kk][3], b0, b1);
                else          MMA_BF16(acc[nb], ar[kk][0], ar[kk][1], ar[kk][2], ar[kk][3], b0, b1);
            }
        }

        __nv_bfloat16* dst = (seg == 0) ? g_Qb : ((seg == 1) ? g_Kb : g_Vb);
#pragma unroll
        for (int nb = 0; nb < 8; nb++) {
            int col = nb*8 + 2*(l & 3);
            float bv0 = bs[seg*64 + col], bv1 = bs[seg*64 + col + 1];
            uint32_t lo, hi;
            CVT_BF16X2(lo, acc[nb][0] + bv0, acc[nb][1] + bv1);
            CVT_BF16X2(hi, acc[nb][2] + bv0, acc[nb][3] + bv1);
            *(uint32_t*)(dst + (size_t)(t0 + r)*64 + col)     = lo;
            *(uint32_t*)(dst + (size_t)(t0 + r + 8)*64 + col) = hi;
        }
    }
}

// ---------------- kernel 2: warp-MMA flash attention + fused refine -------
#define QOFF   0
#define KOFF   16384
#define VOFF   49152
#define UCOFF  81920
#define ATTN_SMEM (81920 + 1024)

__device__ __forceinline__ void issue_tile(uint32_t smem, int win, int ct, int buf, int tid)
{
    int c0 = ct * 128;
    const char* Kg = (const char*)g_Kb + ((size_t)(win*NTOK + c0))*128;
    const char* Vg = (const char*)g_Vb + ((size_t)(win*NTOK + c0))*128;
    uint32_t kb = smem + KOFF + buf*16384;
    uint32_t vb = smem + VOFF + buf*16384;
#pragma unroll
    for (int i = 0; i < 4; i++) {
        int li = i*256 + tid, r = li >> 3, q = li & 7;
        uint32_t off = r*128 + ((q*16) ^ ((r & 7) << 4));
        CP16(kb + off, Kg + r*128 + q*16);
        CP16(vb + off, Vg + r*128 + q*16);
    }
    if (tid < 128)
        CP4(smem + UCOFF + buf*512 + tid*4, (const char*)(g_U + win*NTOK + c0 + tid));
}

__global__ void __launch_bounds__(256) attn_kernel(const float* __restrict__ x)
{
    extern __shared__ char smc[];
    uint32_t smem = smem_to_u32(smc);
    int tid = threadIdx.x, wid = tid >> 5, l = tid & 31;
    int win = blockIdx.y, r0 = blockIdx.x * 128;
    const float LC = 0.18033688011112042f;   // 0.125 * log2(e)

    {
        const char* Qg = (const char*)g_Qb + ((size_t)(win*NTOK + r0))*128;
#pragma unroll
        for (int i = 0; i < 4; i++) {
            int li = i*256 + tid, r = li >> 3, q = li & 7;
            CP16(smem + QOFF + r*128 + ((q*16) ^ ((r & 7) << 4)), Qg + r*128 + q*16);
        }
        issue_tile(smem, win, 0, 0, tid);
        CP_COMMIT();
    }

    int row_a = wid*16 + (l >> 2);
    bool urow0 = g_U[win*NTOK + r0 + row_a]     > -1.f;
    bool urow1 = g_U[win*NTOK + r0 + row_a + 8] > -1.f;

    CP_WAIT0();
    __syncthreads();

    uint32_t qa[4][4];
    {
        int m = l >> 3;
        int qrow = wid*16 + (m & 1)*8 + (l & 7);
        uint32_t xr = (uint32_t)(l & 7) << 4;
#pragma unroll
        for (int kk = 0; kk < 4; kk++) {
            uint32_t addr = smem + QOFF + qrow*128 + (((uint32_t)(kk*32 + (m >> 1)*16)) ^ xr);
            LDSM_X4(qa[kk][0], qa[kk][1], qa[kk][2], qa[kk][3], addr);
        }
    }

    issue_tile(smem, win, 1, 1, tid);
    CP_COMMIT();

    float o[8][4];
#pragma unroll
    for (int j = 0; j < 8; j++)
#pragma unroll
        for (int c = 0; c < 4; c++) o[j][c] = 0.f;
    float rsum0 = 0.f, rsum1 = 0.f;

    int m = l >> 3;
    uint32_t xr = (uint32_t)(l & 7) << 4;
    int nrow_b = (m >> 1)*8 + (l & 7);
    int krow_b = (m & 1)*8 + (l & 7);
    const float* ucsm = (const float*)(smc + UCOFF);

#pragma unroll 1
    for (int ct = 0; ct < 18; ct++) {
        uint32_t kb = smem + KOFF + (ct & 1)*16384;
        uint32_t vb = smem + VOFF + (ct & 1)*16384;

        float s[16][4];
#pragma unroll
        for (int j = 0; j < 16; j++)
#pragma unroll
            for (int c = 0; c < 4; c++) s[j][c] = 0.f;

#pragma unroll
        for (int kk = 0; kk < 4; kk++) {
            uint32_t cb = ((uint32_t)(kk*32 + (m & 1)*16)) ^ xr;
#pragma unroll
            for (int jb = 0; jb < 8; jb++) {
                uint32_t addr = kb + (16*jb + nrow_b)*128 + cb;
                uint32_t b0, b1, b2, b3;
                LDSM_X4(b0, b1, b2, b3, addr);
                MMA_BF16(s[2*jb],   qa[kk][0], qa[kk][1], qa[kk][2], qa[kk][3], b0, b1);
                MMA_BF16(s[2*jb+1], qa[kk][0], qa[kk][1], qa[kk][2], qa[kk][3], b2, b3);
            }
        }

        const float* ucb = ucsm + (ct & 1)*128 + 2*(l & 3);
        uint32_t pc01[16], pc23[16];
#pragma unroll
        for (int j = 0; j < 16; j++) {
            float2 cm = *(const float2*)(ucb + 8*j);
            float p0, p1, p2, p3;
            EX2F(p0, fmaf(s[j][0], LC, cm.x)); p0 = urow0 ? p0 : 1.f;
            EX2F(p1, fmaf(s[j][1], LC, cm.y)); p1 = urow0 ? p1 : 1.f;
            EX2F(p2, fmaf(s[j][2], LC, cm.x)); p2 = urow1 ? p2 : 1.f;
            EX2F(p3, fmaf(s[j][3], LC, cm.y)); p3 = urow1 ? p3 : 1.f;
            rsum0 += p0 + p1;
            rsum1 += p2 + p3;
            CVT_BF16X2(pc01[j], p0, p1);
            CVT_BF16X2(pc23[j], p2, p3);
        }

#pragma unroll
        for (int kc = 0; kc < 8; kc++) {
            uint32_t ra = vb + (16*kc + krow_b)*128;
#pragma unroll
            for (int jb = 0; jb < 4; jb++) {
                uint32_t addr = ra + (((uint32_t)(jb*32 + (m >> 1)*16)) ^ xr);
                uint32_t v0, v1, v2, v3;
                LDSM_X4T(v0, v1, v2, v3, addr);
                MMA_BF16(o[2*jb],   pc01[2*kc], pc23[2*kc], pc01[2*kc+1], pc23[2*kc+1], v0, v1);
                MMA_BF16(o[2*jb+1], pc01[2*kc], pc23[2*kc], pc01[2*kc+1], pc23[2*kc+1], v2, v3);
            }
        }

        __syncthreads();
        if (ct + 2 < 18) { issue_tile(smem, win, ct + 2, ct & 1, tid); CP_COMMIT(); }
        if (ct + 1 < 18) {
            if (ct + 2 < 18) { CP_WAIT1(); } else { CP_WAIT0(); }
            __syncthreads();
        }
    }

    rsum0 += __shfl_xor_sync(0xffffffffu, rsum0, 1);
    rsum0 += __shfl_xor_sync(0xffffffffu, rsum0, 2);
    rsum1 += __shfl_xor_sync(0xffffffffu, rsum1, 1);
    rsum1 += __shfl_xor_sync(0xffffffffu, rsum1, 2);
    float inv0 = 1.f / rsum0, inv1 = 1.f / rsum1;

    // fused refine: refined = x + (O/rsum)*M^T + b2
    __syncthreads();
    {
        const char* Mg = (const char*)g_Mb;
#pragma unroll
        for (int i = 0; i < 2; i++) {
            int li = i*256 + tid, r = li >> 3, q = li & 7;
            CP16(smem + QOFF + r*128 + ((q*16) ^ ((r & 7) << 4)), Mg + r*128 + q*16);
        }
        CP_COMMIT(); CP_WAIT0();
    }
    __syncthreads();

    uint32_t af[4][4];
#pragma unroll
    for (int kk = 0; kk < 4; kk++) {
        CVT_BF16X2(af[kk][0], o[2*kk][0]*inv0,   o[2*kk][1]*inv0);
        CVT_BF16X2(af[kk][1], o[2*kk][2]*inv1,   o[2*kk][3]*inv1);
        CVT_BF16X2(af[kk][2], o[2*kk+1][0]*inv0, o[2*kk+1][1]*inv0);
        CVT_BF16X2(af[kk][3], o[2*kk+1][2]*inv1, o[2*kk+1][3]*inv1);
    }

    float dd[8][4];
#pragma unroll
    for (int j = 0; j < 8; j++)
#pragma unroll
        for (int c = 0; c < 4; c++) dd[j][c] = 0.f;

#pragma unroll
    for (int kk = 0; kk < 4; kk++) {
        uint32_t cb = ((uint32_t)(kk*32 + (m & 1)*16)) ^ xr;
#pragma unroll
        for (int jb = 0; jb < 4; jb++) {
            uint32_t addr = smem + QOFF + (16*jb + nrow_b)*128 + cb;
            uint32_t b0, b1, b2, b3;
            LDSM_X4(b0, b1, b2, b3, addr);
            MMA_BF16(dd[2*jb],   af[kk][0], af[kk][1], af[kk][2], af[kk][3], b0, b1);
            MMA_BF16(dd[2*jb+1], af[kk][0], af[kk][1], af[kk][2], af[kk][3], b2, b3);
        }
    }

    int n0 = r0 + row_a;
    int n1 = n0 + 8;
    int px0 = ((win>>2)*WS + n0/WS)*HW + (win&3)*WS + n0%WS;
    int px1 = ((win>>2)*WS + n1/WS)*HW + (win&3)*WS + n1%WS;
#pragma unroll
    for (int jb = 0; jb < 4; jb++) {
#pragma unroll
        for (int hh = 0; hh < 2; hh++) {
            int c = 16*jb + 8*hh + 2*(l & 3);
            int j = 2*jb + hh;
            float2 b2v = *(const float2*)(g_b2 + c);
            g_ref[(size_t)c*NPIX + px0]     = x[(size_t)c*NPIX + px0]     + dd[j][0] + b2v.x;
            g_ref[(size_t)(c+1)*NPIX + px0] = x[(size_t)(c+1)*NPIX + px0] + dd[j][1] + b2v.y;
            g_ref[(size_t)c*NPIX + px1]     = x[(size_t)c*NPIX + px1]     + dd[j][2] + b2v.x;
            g_ref[(size_t)(c+1)*NPIX + px1] = x[(size_t)(c+1)*NPIX + px1] + dd[j][3] + b2v.y;
        }
    }
}

// ---------------- kernel 3: conv3x3 tf32 implicit GEMM --------------------
// All weights resident in smem; double-buffered cp.async input tiles.
#define CONV_SMEM ((41472 + 2*3264 + 128) * 4)
__device__ __forceinline__ void conv_stage(uint32_t smem, int y0, int cx0, int kc, int tid)
{
    uint32_t dbase = smem + (41472 + (kc & 1)*3264)*4;
    for (int idx = tid; idx < 2720; idx += 256) {
        int ci = idx / 340, rem = idx % 340, ry = rem / 34, rcx = rem % 34;
        int gy = y0 - 1 + ry, gx = cx0 - 1 + rcx;
        bool ok = (gy >= 0) && (gy < HW) && (gx >= 0) && (gx < HW);
        const float* src = ok ? (g_ref + (size_t)(kc*8 + ci)*NPIX + gy*HW + gx)
                              : (const float*)g_ref;
        CPZ(dbase + (ci*408 + ry*40 + rcx)*4, src, ok ? 4u : 0u);
    }
}

__global__ void __launch_bounds__(256) conv_kernel(
    const float* __restrict__ b3, const float* __restrict__ w4,
    const float* __restrict__ b4v, float* __restrict__ out)
{
    extern __shared__ float csm[];
    float* ws  = csm;                    // [8 chunks][9*8*72]
    float* b3s = csm + 41472 + 2*3264;
    float* w4s = b3s + 64;
    uint32_t smem = smem_to_u32(csm);

    int tid = threadIdx.x, wid = tid >> 5, l = tid & 31;
    int cx0 = blockIdx.x*32, y0 = blockIdx.y*8;
    if (tid < 64) { b3s[tid] = b3[tid]; w4s[tid] = w4[tid]; }

    // all weights via cp.async (pre-rounded tf32 in global)
    for (int i4 = tid; i4 < 9216; i4 += 256) {
        int idx = i4*4;
        int c = idx / 576, r = idx % 576, tap = r >> 6, o = r & 63;
        int dstw = (c >> 3)*5184 + (tap*8 + (c & 7))*72 + o;
        CP16(smem + dstw*4, g_W3t + idx);
    }
    conv_stage(smem, y0, cx0, 0, tid);
    CP_COMMIT();

    float acc[2][8][4];
#pragma unroll
    for (int mb = 0; mb < 2; mb++)
#pragma unroll
        for (int nb = 0; nb < 8; nb++)
#pragma unroll
            for (int c = 0; c < 4; c++) acc[mb][nb][c] = 0.f;

    for (int kc = 0; kc < 8; kc++) {
        CP_WAIT0();
        __syncthreads();
        if (kc < 7) { conv_stage(smem, y0, cx0, kc + 1, tid); CP_COMMIT(); }

        const float* in_t = csm + 41472 + (kc & 1)*3264;
        const float* wck  = ws + kc*5184;
#pragma unroll
        for (int tap = 0; tap < 9; tap++) {
            const int dyv = tap / 3, dxv = tap % 3;
            const float* wb = wck + tap*576;
            uint32_t b0a[8], b1a[8];
#pragma unroll
            for (int nb = 0; nb < 8; nb++) {
                b0a[nb] = __float_as_uint(wb[(l & 3)*72 + (l >> 2) + 8*nb]);
                b1a[nb] = __float_as_uint(wb[((l & 3) + 4)*72 + (l >> 2) + 8*nb]);
            }
            int rowoff = (wid + dyv)*40 + dxv;
#pragma unroll
            for (int mb = 0; mb < 2; mb++) {
                int cb = 16*mb + (l >> 2) + rowoff;
                uint32_t a0 = tf32r(in_t[(l & 3)*408 + cb]);
                uint32_t a1 = tf32r(in_t[(l & 3)*408 + cb + 8]);
                uint32_t a2 = tf32r(in_t[((l & 3) + 4)*408 + cb]);
                uint32_t a3 = tf32r(in_t[((l & 3) + 4)*408 + cb + 8]);
#pragma unroll
                for (int nb = 0; nb < 8; nb++)
                    MMA_TF32(acc[mb][nb], a0, a1, a2, a3, b0a[nb], b1a[nb]);
            }
        }
    }

    int y = y0 + wid;
    float b4 = b4v[0];
    float s[2][2] = {{0.f, 0.f}, {0.f, 0.f}};
#pragma unroll
    for (int mb = 0; mb < 2; mb++) {
        int x1 = cx0 + 16*mb + (l >> 2);
        int x2 = x1 + 8;
#pragma unroll
        for (int nb = 0; nb < 8; nb++) {
            int oc = 8*nb + 2*(l & 3);
            float r00 = fmaxf(acc[mb][nb][0] + b3s[oc],   0.f);
            float r01 = fmaxf(acc[mb][nb][1] + b3s[oc+1], 0.f);
            float r10 = fmaxf(acc[mb][nb][2] + b3s[oc],   0.f);
            float r11 = fmaxf(acc[mb][nb][3] + b3s[oc+1], 0.f);
            out[(size_t)oc*NPIX     + y*HW + x1] = r00;
            out[(size_t)(oc+1)*NPIX + y*HW + x1] = r01;
            out[(size_t)oc*NPIX     + y*HW + x2] = r10;
            out[(size_t)(oc+1)*NPIX + y*HW + x2] = r11;
            s[mb][0] += r00*w4s[oc] + r01*w4s[oc+1];
            s[mb][1] += r10*w4s[oc] + r11*w4s[oc+1];
        }
    }
#pragma unroll
    for (int mb = 0; mb < 2; mb++) {
#pragma unroll
        for (int h = 0; h < 2; h++) {
            s[mb][h] += __shfl_xor_sync(0xffffffffu, s[mb][h], 1);
            s[mb][h] += __shfl_xor_sync(0xffffffffu, s[mb][h], 2);
        }
    }
    if ((l & 3) == 0) {
#pragma unroll
        for (int mb = 0; mb < 2; mb++) {
            int x1 = cx0 + 16*mb + (l >> 2);
            out[(size_t)64*NPIX + y*HW + x1]     = s[mb][0] + b4;
            out[(size_t)64*NPIX + y*HW + x1 + 8] = s[mb][1] + b4;
        }
    }
    {
        int yy = y0 + (tid >> 5), xx = cx0 + (tid & 31);
        int ry = yy % WS, rx = xx % WS;
        float pm = ((ry == 0) | (ry == WS-1) | (rx == 0) | (rx == WS-1)) ? 0.6f : 1.0f;
        out[(size_t)65*NPIX + yy*HW + xx] = pm;
    }
}

// ---------------- launch ---------------------------------------------------
extern "C" void kernel_launch(void* const* d_in, const int* in_sizes, int n_in,
                              void* d_out, int out_size)
{
    const float* x    = (const float*)d_in[0];
    const float* rf   = (const float*)d_in[1];
    const float* unc  = (const float*)d_in[2];
    const float* ipw  = (const float*)d_in[3];
    const float* ipb  = (const float*)d_in[4];
    const float* wout = (const float*)d_in[5];
    const float* bout = (const float*)d_in[6];
    const float* w1   = (const float*)d_in[7];
    const float* b1   = (const float*)d_in[8];
    const float* w3   = (const float*)d_in[9];
    const float* b3   = (const float*)d_in[10];
    const float* w4   = (const float*)d_in[11];
    const float* b4   = (const float*)d_in[12];
    float* out = (float*)d_out;

    static bool attr_set = false;
    if (!attr_set) {
        cudaFuncSetAttribute(attn_kernel, cudaFuncAttributeMaxDynamicSharedMemorySize, ATTN_SMEM);
        cudaFuncSetAttribute(conv_kernel, cudaFuncAttributeMaxDynamicSharedMemorySize, CONV_SMEM);
        cudaFuncSetAttribute(qkv_kernel, cudaFuncAttributeMaxDynamicSharedMemorySize, QKV_SMEM);
        attr_set = true;
    }

    prep_kernel<<<64, 64>>>(w1, b1, wout, bout, w3, ipw);
    qkv_kernel<<<288, 256, QKV_SMEM>>>(x, rf, unc, ipb);
    dim3 ag(18, 16);
    attn_kernel<<<ag, 256, ATTN_SMEM>>>(x);
    dim3 cg(6, 24);
    conv_kernel<<<cg, 256, CONV_SMEM>>>(b3, w4, b4, out);
}